// round 16
// baseline (speedup 1.0000x reference)
#include <cuda_runtime.h>
#include <cstdint>

#define Bb   2
#define Tt   2048
#define Dd   1024
#define Hh   16
#define HDIM 64
#define MTOT (Bb*Tt)        // 4096
#define NFLASH 512          // flash items (16 qt x 16 h x 2 b)
#define NUNITS (NFLASH + 256)   // + Wo tiles (32 by x 8 bx)

// Scratch (allocation-free rule: __device__ globals)
__device__ float g_q[Bb*Hh*Tt*HDIM];     // d-dim permuted
__device__ float g_k[Bb*Hh*Tt*HDIM];     // d-dim permuted
__device__ float g_vt[Bb*Hh*HDIM*Tt];    // transposed V [b][h][d][tperm]
__device__ float g_ctx[Bb*Tt*Dd];        // d-dim permuted (A of Wo gemm)
__device__ float g_xr[MTOT*Dd];          // tf32-rounded x, k-perm
__device__ float g_wt[4][Dd*Dd];         // tf32-rounded W^T [n][k], k-perm
__device__ int   g_ctr;                  // fused work counter
__device__ int   g_row_done[32];         // per (b,qt) row-block: # flash items done

// ---- helpers --------------------------------------------------------------
__device__ __forceinline__ unsigned rtf_u(float x) {
    unsigned u; asm("cvt.rna.tf32.f32 %0, %1;" : "=r"(u) : "f"(x)); return u;
}
__device__ __forceinline__ float rtf(float x) { return __uint_as_float(rtf_u(x)); }
__device__ __forceinline__ unsigned f2u(float x) { return __float_as_uint(x); }
__device__ __forceinline__ void cpa16(void* dst, const void* src) {
    unsigned s = (unsigned)__cvta_generic_to_shared(dst);
    asm volatile("cp.async.cg.shared.global [%0], [%1], 16;\n" :: "r"(s), "l"(src));
}
__device__ __forceinline__ float ex2(float x) {
    float y; asm("ex2.approx.ftz.f32 %0, %1;" : "=f"(y) : "f"(x)); return y;
}
// position p holds original k-offset (p>>1)+4*(p&1)  (within each 8-block)
__device__ __forceinline__ int korig(int p) {
    return (p & ~7) + (((p & 7) >> 1)) + 4 * (p & 1);
}
// original offset c stored at position 2*(c&3)+((c>>2)&1)
__device__ __forceinline__ int kpos(int c) {
    return (c & ~7) + 2 * (c & 3) + ((c >> 2) & 1);
}
// mma.sync m16n8k8 tf32: D += A*B
__device__ __forceinline__ void mma8(float* d, const unsigned* a, const unsigned* b) {
    asm volatile(
        "mma.sync.aligned.m16n8k8.row.col.f32.tf32.tf32.f32 "
        "{%0,%1,%2,%3}, {%4,%5,%6,%7}, {%8,%9}, {%0,%1,%2,%3};\n"
        : "+f"(d[0]), "+f"(d[1]), "+f"(d[2]), "+f"(d[3])
        : "r"(a[0]), "r"(a[1]), "r"(a[2]), "r"(a[3]), "r"(b[0]), "r"(b[1]));
}

// ---------------------------------------------------------------------------
// prep: grid (32, 32, 5), block 256.
//   z in 0..3 : g_wt[z][n][p] = rtf(W_z[k0+korig(p)][n])  (transpose + k-perm)
//   z == 4    : g_xr[m][p] = rtf(x[m][korig(p)]) + reset counters.
// ---------------------------------------------------------------------------
__global__ void prep(const float* __restrict__ x,
                     const float* __restrict__ wq, const float* __restrict__ wk,
                     const float* __restrict__ wv, const float* __restrict__ wo)
{
    __shared__ float t[32][33];
    const int z = blockIdx.z;
    if (z < 4) {
        const float* W = (z == 0) ? wq : (z == 1) ? wk : (z == 2) ? wv : wo;
        float* D = g_wt[z];
        int k0 = blockIdx.x * 32, n0 = blockIdx.y * 32;
        int tx = threadIdx.x & 31, ty = threadIdx.x >> 5;   // (32,8)
        #pragma unroll
        for (int i = 0; i < 32; i += 8)
            t[ty + i][tx] = rtf(W[(size_t)(k0 + ty + i) * 1024 + n0 + tx]);
        __syncthreads();
        int src = korig(tx);
        #pragma unroll
        for (int i = 0; i < 32; i += 8)
            D[(size_t)(n0 + ty + i) * 1024 + k0 + tx] = t[src][ty + i];
    } else {
        int bid = blockIdx.y * 32 + blockIdx.x;             // 0..1023
        if (bid == 0) {
            if (threadIdx.x == 0) g_ctr = 0;
            if (threadIdx.x < 32) g_row_done[threadIdx.x] = 0;
        }
        #pragma unroll
        for (int c = 0; c < 4; c++) {
            int i = ((bid * 4 + c) * 256 + threadIdx.x) * 4;
            int m = i >> 10, kp = i & 1023;
            const float* row = x + (size_t)m * 1024;
            float4 o;
            o.x = rtf(row[korig(kp)]);
            o.y = rtf(row[korig(kp + 1)]);
            o.z = rtf(row[korig(kp + 2)]);
            o.w = rtf(row[korig(kp + 3)]);
            *(float4*)&g_xr[i] = o;
        }
    }
}

// ---------------------------------------------------------------------------
// QKV GEMM (tf32 mma.sync, float2 frag loads, 2-stage cp.async) — R13 config.
// z∈{0,1} -> Q/K head-split d-permuted; z==2 -> V transposed+key-perm.
// ---------------------------------------------------------------------------
#define AS_ST (128*40)
#define WS_ST (128*40)
#define GSTG  2
#define GSMEM (GSTG * (AS_ST + WS_ST) * 4)     // 81920 B

__global__ __launch_bounds__(256, 2)
void gemm_qkv(const float* __restrict__ A,
              const float* __restrict__ W0, const float* __restrict__ W1,
              const float* __restrict__ W2,
              float* __restrict__ C0, float* __restrict__ C1,
              float* __restrict__ C2)
{
    extern __shared__ float sh[];
    float* Apool = sh;
    float* Wpool = sh + GSTG * AS_ST;

    const float* W = (blockIdx.z == 0) ? W0 : (blockIdx.z == 1) ? W1 : W2;
    float*       C = (blockIdx.z == 0) ? C0 : (blockIdx.z == 1) ? C1 : C2;

    const int tid = threadIdx.x;
    const int lane = tid & 31, warp = tid >> 5;
    const int g = lane >> 2, tg = lane & 3;
    const int wm = warp >> 2;
    const int wn = warp & 3;
    const int m0 = blockIdx.y * 128;
    const int n0 = blockIdx.x * 128;

    float acc[4][4][4];
    #pragma unroll
    for (int mt = 0; mt < 4; mt++)
        #pragma unroll
        for (int nt = 0; nt < 4; nt++)
            #pragma unroll
            for (int c = 0; c < 4; c++) acc[mt][nt][c] = 0.f;

    auto ISSUE = [&](int it) {
        const int k0 = it * 32;
        float* Ab = Apool + (it & 1) * AS_ST;
        float* Wb = Wpool + (it & 1) * WS_ST;
        #pragma unroll
        for (int j = 0; j < 4; j++) {
            int id = j * 256 + tid;
            int r = id >> 3, c = id & 7;
            cpa16(&Ab[r * 40 + c * 4], &A[(size_t)(m0 + r) * 1024 + k0 + c * 4]);
        }
        #pragma unroll
        for (int j = 0; j < 4; j++) {
            int id = j * 256 + tid;
            int r = id >> 3, c = id & 7;
            cpa16(&Wb[r * 40 + c * 4], &W[(size_t)(n0 + r) * 1024 + k0 + c * 4]);
        }
    };

    ISSUE(0); asm volatile("cp.async.commit_group;\n");

    for (int it = 0; it < 32; it++) {
        asm volatile("cp.async.wait_group 0;\n");
        __syncthreads();
        if (it + 1 < 32) {
            ISSUE(it + 1);
            asm volatile("cp.async.commit_group;\n");
        }

        const float* Ab = Apool + (it & 1) * AS_ST;
        const float* Wb = Wpool + (it & 1) * WS_ST;
        #pragma unroll
        for (int kk = 0; kk < 32; kk += 8) {
            unsigned a[4][4], b[4][2];
            #pragma unroll
            for (int mt = 0; mt < 4; mt++) {
                int rb = wm * 64 + mt * 16;
                float2 lo = *(const float2*)&Ab[(rb + g    ) * 40 + kk + 2 * tg];
                float2 hi = *(const float2*)&Ab[(rb + g + 8) * 40 + kk + 2 * tg];
                a[mt][0] = f2u(lo.x); a[mt][1] = f2u(hi.x);
                a[mt][2] = f2u(lo.y); a[mt][3] = f2u(hi.y);
            }
            #pragma unroll
            for (int nt = 0; nt < 4; nt++) {
                int nb = wn * 32 + nt * 8;
                float2 bp = *(const float2*)&Wb[(nb + g) * 40 + kk + 2 * tg];
                b[nt][0] = f2u(bp.x); b[nt][1] = f2u(bp.y);
            }
            #pragma unroll
            for (int mt = 0; mt < 4; mt++)
                #pragma unroll
                for (int nt = 0; nt < 4; nt++)
                    mma8(acc[mt][nt], a[mt], b[nt]);
        }
    }

    #pragma unroll
    for (int mt = 0; mt < 4; mt++) {
        #pragma unroll
        for (int nt = 0; nt < 4; nt++) {
            int colL = wn * 32 + nt * 8 + 2 * tg;
            int rA = m0 + wm * 64 + mt * 16 + g;
            int rB = rA + 8;
            float c0 = acc[mt][nt][0], c1 = acc[mt][nt][1];
            float c2 = acc[mt][nt][2], c3 = acc[mt][nt][3];
            int gc = n0 + colL;
            int h = gc >> 6, d = gc & 63;
            int bA = rA >> 11, tA = rA & 2047;
            int bB = rB >> 11, tB = rB & 2047;
            if (blockIdx.z == 2) {
                size_t baseA = ((size_t)(bA * Hh + h) * HDIM + d) * Tt;
                size_t baseB = ((size_t)(bB * Hh + h) * HDIM + d) * Tt;
                int tpA = kpos(tA), tpB = kpos(tB);
                C[baseA      + tpA] = rtf(c0);
                C[baseA + Tt + tpA] = rtf(c1);
                C[baseB      + tpB] = rtf(c2);
                C[baseB + Tt + tpB] = rtf(c3);
            } else {
                float* dA = &C[((size_t)(bA * Hh + h) * Tt + tA) * HDIM];
                float* dB = &C[((size_t)(bB * Hh + h) * Tt + tB) * HDIM];
                int p0 = kpos(d), p1 = kpos(d + 1);
                dA[p0] = rtf(c0); dA[p1] = rtf(c1);
                dB[p0] = rtf(c2); dB[p1] = rtf(c3);
            }
        }
    }
}

// ---------------------------------------------------------------------------
// FUSED persistent kernel: units 0..511 = flash items (LPT, heaviest qt first),
// units 512..767 = Wo tiles (ordered to match flash row-completion order).
// Wo tile spins until all 16 flash items of its row-block are done.
// smem = flash layout (110592 B), 2 CTAs/SM.
// ---------------------------------------------------------------------------
#define FSMEM ((128*72 + 2*64*72 + 2*64*72) * 4)   // 110592

__global__ __launch_bounds__(256, 2)
void fused_fw(const float* __restrict__ q, const float* __restrict__ k,
              const float* __restrict__ vt, float* __restrict__ ctx,
              const float* __restrict__ wo, const float* __restrict__ bias,
              float* __restrict__ out)
{
    extern __shared__ float sm[];
    __shared__ int s_item;

    const int tid  = threadIdx.x;
    const int lane = tid & 31, warp = tid >> 5;
    const int g = lane >> 2, tg = lane & 3;
    const float QSC = 0.18033688011112042f;   // (1/sqrt(64))*log2(e)

    for (;;) {
        if (tid == 0) s_item = atomicAdd(&g_ctr, 1);
        __syncthreads();                       // item visible; prior item's smem done
        const int u = s_item;
        if (u >= NUNITS) break;

        if (u < NFLASH) {
            // ---------------- flash item ----------------
            float* Qs  = sm;                   // [128][72]
            float* Ks  = sm + 128 * 72;        // [2][64][72]
            float* Vtb = Ks + 2 * 64 * 72;     // [2][64][72]

            const int wq = warp * 16;
            const int qt = 15 - (u >> 5);      // heaviest first
            const int bh = u & 31;
            const int h = bh & 15, b = bh >> 4;
            const int q0 = qt * 128;

            const size_t bho = (size_t)(b * Hh + h) * (Tt * HDIM);
            const float* qb = q + bho;
            const float* kb = k + bho;
            const float* vp = vt + bho;        // [d][tperm], d-major

            #pragma unroll
            for (int i = 0; i < 8; i++) {
                int idx = i * 256 + tid;
                int r = idx >> 4, c4 = (idx & 15) * 4;
                float4 x = *(const float4*)&qb[(size_t)(q0 + r) * HDIM + c4];
                *(float4*)&Qs[r * 72 + c4] = make_float4(rtf(x.x * QSC), rtf(x.y * QSC),
                                                         rtf(x.z * QSC), rtf(x.w * QSC));
            }

            auto ISSKV = [&](int kt, int s) {
                const int k0 = kt * 64;
                #pragma unroll
                for (int i = 0; i < 4; i++) {
                    int id = i * 256 + tid;
                    int r = id >> 4, c4 = (id & 15) * 4;
                    cpa16(&Ks [s * (64*72) + r * 72 + c4], &kb[(size_t)(k0 + r) * HDIM + c4]);
                    cpa16(&Vtb[s * (64*72) + r * 72 + c4], &vp[(size_t)r * Tt + k0 + c4]);
                }
            };

            float mrow[2] = {-1e30f, -1e30f};
            float lrow[2] = {0.f, 0.f};
            float O[8][4];
            #pragma unroll
            for (int nt = 0; nt < 8; nt++)
                #pragma unroll
                for (int j = 0; j < 4; j++) O[nt][j] = 0.f;

            const int ktmax = 2 * qt + 1;
            ISSKV(0, 0); asm volatile("cp.async.commit_group;\n");

            for (int kt = 0; kt <= ktmax; kt++) {
                const int s = kt & 1;
                const int k0 = kt * 64;
                asm volatile("cp.async.wait_group 0;\n");
                __syncthreads();
                if (kt < ktmax) {
                    ISSKV(kt + 1, s ^ 1);
                    asm volatile("cp.async.commit_group;\n");
                }

                if (k0 <= q0 + wq + 15) {
                    const float* Kb = Ks  + s * (64*72);
                    const float* Vb = Vtb + s * (64*72);

                    float S[8][4];
                    #pragma unroll
                    for (int nt = 0; nt < 8; nt++)
                        #pragma unroll
                        for (int j = 0; j < 4; j++) S[nt][j] = 0.f;

                    #pragma unroll
                    for (int kk = 0; kk < 64; kk += 8) {
                        float2 qlo = *(const float2*)&Qs[(wq + g    ) * 72 + kk + 2 * tg];
                        float2 qhi = *(const float2*)&Qs[(wq + g + 8) * 72 + kk + 2 * tg];
                        unsigned a[4] = { f2u(qlo.x), f2u(qhi.x), f2u(qlo.y), f2u(qhi.y) };
                        #pragma unroll
                        for (int nt = 0; nt < 8; nt++) {
                            float2 kp = *(const float2*)&Kb[(nt * 8 + g) * 72 + kk + 2 * tg];
                            unsigned bv[2] = { f2u(kp.x), f2u(kp.y) };
                            mma8(S[nt], a, bv);
                        }
                    }

                    if (k0 + 63 > q0 + wq) {
                        int qA = q0 + wq + g, qB = qA + 8;
                        #pragma unroll
                        for (int nt = 0; nt < 8; nt++) {
                            int c = k0 + nt * 8 + 2 * tg;
                            if (c     > qA) S[nt][0] = -1e30f;
                            if (c + 1 > qA) S[nt][1] = -1e30f;
                            if (c     > qB) S[nt][2] = -1e30f;
                            if (c + 1 > qB) S[nt][3] = -1e30f;
                        }
                    }

                    float mA = -1e30f, mB = -1e30f;
                    #pragma unroll
                    for (int nt = 0; nt < 8; nt++) {
                        mA = fmaxf(mA, fmaxf(S[nt][0], S[nt][1]));
                        mB = fmaxf(mB, fmaxf(S[nt][2], S[nt][3]));
                    }
                    #pragma unroll
                    for (int o = 1; o <= 2; o <<= 1) {
                        mA = fmaxf(mA, __shfl_xor_sync(0xffffffffu, mA, o));
                        mB = fmaxf(mB, __shfl_xor_sync(0xffffffffu, mB, o));
                    }
                    float nmA = fmaxf(mrow[0], mA), nmB = fmaxf(mrow[1], mB);
                    float sA = 0.f, sB = 0.f;
                    #pragma unroll
                    for (int nt = 0; nt < 8; nt++) {
                        S[nt][0] = ex2(S[nt][0] - nmA);
                        S[nt][1] = ex2(S[nt][1] - nmA);
                        S[nt][2] = ex2(S[nt][2] - nmB);
                        S[nt][3] = ex2(S[nt][3] - nmB);
                        sA += S[nt][0] + S[nt][1];
                        sB += S[nt][2] + S[nt][3];
                    }
                    #pragma unroll
                    for (int o = 1; o <= 2; o <<= 1) {
                        sA += __shfl_xor_sync(0xffffffffu, sA, o);
                        sB += __shfl_xor_sync(0xffffffffu, sB, o);
                    }
                    float scA = ex2(mrow[0] - nmA), scB = ex2(mrow[1] - nmB);
                    lrow[0] = lrow[0] * scA + sA;  mrow[0] = nmA;
                    lrow[1] = lrow[1] * scB + sB;  mrow[1] = nmB;
                    #pragma unroll
                    for (int nt = 0; nt < 8; nt++) {
                        O[nt][0] *= scA; O[nt][1] *= scA;
                        O[nt][2] *= scB; O[nt][3] *= scB;
                    }

                    const int src0 = (lane & ~3) | (tg >> 1);
                    const int src1 = src0 + 2;
                    const bool odd = tg & 1;
                    #pragma unroll
                    for (int j = 0; j < 8; j++) {
                        float v00 = __shfl_sync(0xffffffffu, S[j][0], src0);
                        float v01 = __shfl_sync(0xffffffffu, S[j][1], src0);
                        float v02 = __shfl_sync(0xffffffffu, S[j][2], src0);
                        float v03 = __shfl_sync(0xffffffffu, S[j][3], src0);
                        float v10 = __shfl_sync(0xffffffffu, S[j][0], src1);
                        float v11 = __shfl_sync(0xffffffffu, S[j][1], src1);
                        float v12 = __shfl_sync(0xffffffffu, S[j][2], src1);
                        float v13 = __shfl_sync(0xffffffffu, S[j][3], src1);
                        unsigned a[4];
                        a[0] = rtf_u(odd ? v01 : v00);
                        a[1] = rtf_u(odd ? v03 : v02);
                        a[2] = rtf_u(odd ? v11 : v10);
                        a[3] = rtf_u(odd ? v13 : v12);
                        #pragma unroll
                        for (int nt = 0; nt < 8; nt++) {
                            float2 vv = *(const float2*)&Vb[(nt * 8 + g) * 72 + 8 * j + 2 * tg];
                            unsigned bv[2] = { f2u(vv.x), f2u(vv.y) };
                            mma8(O[nt], a, bv);
                        }
                    }
                }
            }

            // normalize + write ctx d-PERMUTED
            float invA = 1.0f / lrow[0], invB = 1.0f / lrow[1];
            int tA = q0 + (warp * 16) + g, tB = tA + 8;
            float* rowA = &ctx[((size_t)b * Tt + tA) * Dd];
            float* rowB = &ctx[((size_t)b * Tt + tB) * Dd];
            #pragma unroll
            for (int nt = 0; nt < 8; nt++) {
                int c = h * HDIM + nt * 8 + 2 * tg;
                int p0 = kpos(c), p1 = kpos(c + 1);
                rowA[p0] = rtf(O[nt][0] * invA);
                rowA[p1] = rtf(O[nt][1] * invA);
                rowB[p0] = rtf(O[nt][2] * invB);
                rowB[p1] = rtf(O[nt][3] * invB);
            }

            // signal row-block completion (release)
            __threadfence();
            __syncthreads();
            if (tid == 0) atomicAdd(&g_row_done[b * 16 + qt], 1);

        } else {
            // ---------------- Wo tile ----------------
            float* Apool = sm;
            float* Wpool = sm + GSTG * AS_ST;

            const int w = u - NFLASH;          // 0..255
            const int rank = w >> 3;           // 0..31, in completion order
            const int qt = 15 - (rank >> 1);
            const int b = rank & 1;
            const int rowIdx = b * 16 + qt;
            const int m0 = b * 2048 + qt * 128;
            const int n0 = (w & 7) * 128;

            if (tid == 0) {
                while (atomicAdd(&g_row_done[rowIdx], 0) < 16) { }
            }
            __syncthreads();
            __threadfence();                   // acquire ordering for ctx reads

            const int wm = warp >> 2;
            const int wn = warp & 3;

            float acc[4][4][4];
            #pragma unroll
            for (int mt = 0; mt < 4; mt++)
                #pragma unroll
                for (int nt = 0; nt < 4; nt++)
                    #pragma unroll
                    for (int c = 0; c < 4; c++) acc[mt][nt][c] = 0.f;

            auto ISSUE = [&](int it) {
                const int k0 = it * 32;
                float* Ab = Apool + (it & 1) * AS_ST;
                float* Wb = Wpool + (it & 1) * WS_ST;
                #pragma unroll
                for (int j = 0; j < 4; j++) {
                    int id = j * 256 + tid;
                    int r = id >> 3, c = id & 7;
                    cpa16(&Ab[r * 40 + c * 4], &ctx[(size_t)(m0 + r) * 1024 + k0 + c * 4]);
                }
                #pragma unroll
                for (int j = 0; j < 4; j++) {
                    int id = j * 256 + tid;
                    int r = id >> 3, c = id & 7;
                    cpa16(&Wb[r * 40 + c * 4], &wo[(size_t)(n0 + r) * 1024 + k0 + c * 4]);
                }
            };

            ISSUE(0); asm volatile("cp.async.commit_group;\n");

            for (int it = 0; it < 32; it++) {
                asm volatile("cp.async.wait_group 0;\n");
                __syncthreads();
                if (it + 1 < 32) {
                    ISSUE(it + 1);
                    asm volatile("cp.async.commit_group;\n");
                }

                const float* Ab = Apool + (it & 1) * AS_ST;
                const float* Wb = Wpool + (it & 1) * WS_ST;
                #pragma unroll
                for (int kk = 0; kk < 32; kk += 8) {
                    unsigned a[4][4], bfr[4][2];
                    #pragma unroll
                    for (int mt = 0; mt < 4; mt++) {
                        int rb = wm * 64 + mt * 16;
                        float2 lo = *(const float2*)&Ab[(rb + g    ) * 40 + kk + 2 * tg];
                        float2 hi = *(const float2*)&Ab[(rb + g + 8) * 40 + kk + 2 * tg];
                        a[mt][0] = f2u(lo.x); a[mt][1] = f2u(hi.x);
                        a[mt][2] = f2u(lo.y); a[mt][3] = f2u(hi.y);
                    }
                    #pragma unroll
                    for (int nt = 0; nt < 4; nt++) {
                        int nb = wn * 32 + nt * 8;
                        float2 bp = *(const float2*)&Wb[(nb + g) * 40 + kk + 2 * tg];
                        bfr[nt][0] = f2u(bp.x); bfr[nt][1] = f2u(bp.y);
                    }
                    #pragma unroll
                    for (int mt = 0; mt < 4; mt++)
                        #pragma unroll
                        for (int nt = 0; nt < 4; nt++)
                            mma8(acc[mt][nt], a[mt], bfr[nt]);
                }
            }

            #pragma unroll
            for (int mt = 0; mt < 4; mt++) {
                #pragma unroll
                for (int nt = 0; nt < 4; nt++) {
                    int colL = wn * 32 + nt * 8 + 2 * tg;
                    int rA = m0 + wm * 64 + mt * 16 + g;
                    int rB = rA + 8;
                    float b0 = bias[n0 + colL], b1 = bias[n0 + colL + 1];
                    *(float2*)&out[(size_t)rA * 1024 + n0 + colL] =
                        make_float2(acc[mt][nt][0] + b0, acc[mt][nt][1] + b1);
                    *(float2*)&out[(size_t)rB * 1024 + n0 + colL] =
                        make_float2(acc[mt][nt][2] + b0, acc[mt][nt][3] + b1);
                }
            }
        }
    }
}

// ---------------------------------------------------------------------------
extern "C" void kernel_launch(void* const* d_in, const int* in_sizes, int n_in,
                              void* d_out, int out_size)
{
    const float* x  = (const float*)d_in[0];
    const float* Wq = (const float*)d_in[1];
    const float* Wk = (const float*)d_in[2];
    const float* Wv = (const float*)d_in[3];
    const float* Wo = (const float*)d_in[4];
    const float* bo = (const float*)d_in[5];
    float* out = (float*)d_out;

    float *pq, *pk, *pvt, *pctx, *pxr, *pwt;
    cudaGetSymbolAddress((void**)&pq,   g_q);
    cudaGetSymbolAddress((void**)&pk,   g_k);
    cudaGetSymbolAddress((void**)&pvt,  g_vt);
    cudaGetSymbolAddress((void**)&pctx, g_ctx);
    cudaGetSymbolAddress((void**)&pxr,  g_xr);
    cudaGetSymbolAddress((void**)&pwt,  g_wt);
    float* wt0 = pwt;
    float* wt1 = pwt + (size_t)Dd*Dd;
    float* wt2 = pwt + 2*(size_t)Dd*Dd;
    float* wt3 = pwt + 3*(size_t)Dd*Dd;

    cudaFuncSetAttribute(gemm_qkv, cudaFuncAttributeMaxDynamicSharedMemorySize, GSMEM);
    cudaFuncSetAttribute(fused_fw, cudaFuncAttributeMaxDynamicSharedMemorySize, FSMEM);

    prep<<<dim3(32, 32, 5), 256>>>(x, Wq, Wk, Wv, Wo);

    gemm_qkv<<<dim3(Dd/128, MTOT/128, 3), 256, GSMEM>>>(
        pxr, wt0, wt1, wt2, pq, pk, pvt);

    fused_fw<<<304, 256, FSMEM>>>(pq, pk, pvt, pctx, wt3, bo, out);
}

// round 17
// speedup vs baseline: 1.8767x; 1.8767x over previous
#include <cuda_runtime.h>
#include <cuda_fp16.h>
#include <cstdint>

#define Bb   2
#define Tt   2048
#define Dd   1024
#define Hh   16
#define HDIM 64
#define MTOT (Bb*Tt)        // 4096
#define NFLASH 512

// Scratch (allocation-free rule: __device__ globals)
__device__ __half g_qh [Bb*Hh*Tt*HDIM];   // d perm16, pre-scaled by QSC
__device__ __half g_kh [Bb*Hh*Tt*HDIM];   // d perm16
__device__ __half g_vth[Bb*Hh*HDIM*Tt];   // V^T, t perm16
__device__ __half g_ctxh[Bb*Tt*Dd];       // k perm16 (A of Wo gemm)
__device__ __half g_xh [MTOT*Dd];         // k perm16
__device__ __half g_wth[4][Dd*Dd];        // W^T [n][k], k perm16
__device__ int    g_ctr;

// ---- helpers --------------------------------------------------------------
__device__ __forceinline__ void cpa16(void* dst, const void* src) {
    unsigned s = (unsigned)__cvta_generic_to_shared(dst);
    asm volatile("cp.async.cg.shared.global [%0], [%1], 16;\n" :: "r"(s), "l"(src));
}
__device__ __forceinline__ float ex2(float x) {
    float y; asm("ex2.approx.ftz.f32 %0, %1;" : "=f"(y) : "f"(x)); return y;
}
// 16-block pair interleave: pos 4t+{0,1} <- cols 2t,2t+1 ; pos 4t+{2,3} <- cols 2t+8,2t+9
__device__ __forceinline__ int korig16(int p) {    // position -> source col
    int t = p >> 2, r = p & 3;
    int s = (r < 2) ? t : t + 4;
    return 2 * s + (r & 1);
}
__device__ __forceinline__ int kpos16(int c) {     // source col -> position
    int s = c >> 1, o = c & 1;
    return (s < 4) ? 4 * s + o : 4 * (s - 4) + 2 + o;
}
__device__ __forceinline__ unsigned h2u(float lo, float hi) {
    __half2 h = __floats2half2_rn(lo, hi);
    return *(unsigned*)&h;
}
// mma.sync m16n8k16 f16 (f32 accum): D += A*B
// A: a0=(g, k=2tg,2tg+1) a1=(g+8, same) a2=(g, k=2tg+8,+9) a3=(g+8, same)
// B: b0=(k=2tg,2tg+1, n=g) b1=(k=2tg+8,+9, n=g)
// C: c0=(g,2tg) c1=(g,2tg+1) c2=(g+8,2tg) c3=(g+8,2tg+1)
__device__ __forceinline__ void mma16(float* d, const unsigned* a, unsigned b0, unsigned b1) {
    asm volatile(
        "mma.sync.aligned.m16n8k16.row.col.f32.f16.f16.f32 "
        "{%0,%1,%2,%3}, {%4,%5,%6,%7}, {%8,%9}, {%0,%1,%2,%3};\n"
        : "+f"(d[0]), "+f"(d[1]), "+f"(d[2]), "+f"(d[3])
        : "r"(a[0]), "r"(a[1]), "r"(a[2]), "r"(a[3]), "r"(b0), "r"(b1));
}

// ---------------------------------------------------------------------------
// prep: grid (32, 32, 5), block 256.
//   z 0..3: g_wth[z][n][p] = half(W_z[k0+korig16][n])  (transpose + perm16)
//   z == 4: g_xh[m][p] = half(x[m][korig16]) + reset counter.
// ---------------------------------------------------------------------------
__global__ void prep(const float* __restrict__ x,
                     const float* __restrict__ wq, const float* __restrict__ wk,
                     const float* __restrict__ wv, const float* __restrict__ wo)
{
    __shared__ float t[32][33];
    const int z = blockIdx.z;
    if (z < 4) {
        const float* W = (z == 0) ? wq : (z == 1) ? wk : (z == 2) ? wv : wo;
        __half* D = g_wth[z];
        int k0 = blockIdx.x * 32, n0 = blockIdx.y * 32;
        int tx = threadIdx.x & 31, ty = threadIdx.x >> 5;   // (32,8)
        #pragma unroll
        for (int i = 0; i < 32; i += 8)
            t[ty + i][tx] = W[(size_t)(k0 + ty + i) * 1024 + n0 + tx];
        __syncthreads();
        int src = (tx & 16) + korig16(tx & 15);
        #pragma unroll
        for (int i = 0; i < 32; i += 8)
            D[(size_t)(n0 + ty + i) * 1024 + k0 + tx] = __float2half(t[src][ty + i]);
    } else {
        int bid = blockIdx.y * 32 + blockIdx.x;             // 0..1023
        if (bid == 0 && threadIdx.x == 0) g_ctr = 0;
        #pragma unroll
        for (int it = 0; it < 2; it++) {
            int base = ((bid * 2 + it) * 256 + threadIdx.x) * 8;   // 8 halves
            int m = base >> 10, kp = base & 1023;
            const float* row = x + (size_t)m * 1024;
            __half hv[8];
            #pragma unroll
            for (int j = 0; j < 8; j++) {
                int p = kp + j;
                hv[j] = __float2half(row[(p & ~15) + korig16(p & 15)]);
            }
            *(uint4*)&g_xh[base] = *(uint4*)hv;
        }
    }
}

// ---------------------------------------------------------------------------
// GEMM (fp16 mma.sync m16n8k16, 2-stage cp.async): 128x128 tile, 256 thr,
// 8 warps (2m x 4n), warp 64x32, 2 CTAs/SM.  Smem stride 48 halves
// (conflict-free per half-warp).  Operands perm16 -> all frags LDS.64.
// mode 0: f32 out + bias.  mode 1: z0 Q (xQSC), z1 K, z2 V->Vt; all half out.
// ---------------------------------------------------------------------------
#define AS_ST (128*48)
#define WS_ST (128*48)
#define GSTG  2
#define GSMEM (GSTG * (AS_ST + WS_ST) * 2)     // 49152 B

__global__ __launch_bounds__(256, 2)
void gemm_mma(const __half* __restrict__ A,
              const __half* __restrict__ W0, const __half* __restrict__ W1,
              const __half* __restrict__ W2,
              void* __restrict__ C0, void* __restrict__ C1, void* __restrict__ C2,
              const float* __restrict__ bias, int mode)
{
    extern __shared__ __half sh[];
    __half* Apool = sh;                  // [2][128][48]
    __half* Wpool = sh + GSTG * AS_ST;   // [2][128][48]  ([n][k])

    const __half* W = (blockIdx.z == 0) ? W0 : (blockIdx.z == 1) ? W1 : W2;
    void*         C = (blockIdx.z == 0) ? C0 : (blockIdx.z == 1) ? C1 : C2;

    const int tid = threadIdx.x;
    const int lane = tid & 31, warp = tid >> 5;
    const int g = lane >> 2, tg = lane & 3;
    const int wm = warp >> 2;
    const int wn = warp & 3;
    const int m0 = blockIdx.y * 128;
    const int n0 = blockIdx.x * 128;
    const float QSC = 0.18033688011112042f;   // (1/sqrt(64))*log2(e)

    float acc[4][4][4];
    #pragma unroll
    for (int mt = 0; mt < 4; mt++)
        #pragma unroll
        for (int nt = 0; nt < 4; nt++)
            #pragma unroll
            for (int c = 0; c < 4; c++) acc[mt][nt][c] = 0.f;

    auto ISSUE = [&](int it) {
        const int k0 = it * 32;
        __half* Ab = Apool + (it & 1) * AS_ST;
        __half* Wb = Wpool + (it & 1) * WS_ST;
        #pragma unroll
        for (int j = 0; j < 2; j++) {          // A: 128 rows x 32 halves (4 chunks)
            int id = j * 256 + tid;
            int r = id >> 2, c = id & 3;
            cpa16(&Ab[r * 48 + c * 8], &A[(size_t)(m0 + r) * 1024 + k0 + c * 8]);
        }
        #pragma unroll
        for (int j = 0; j < 2; j++) {
            int id = j * 256 + tid;
            int r = id >> 2, c = id & 3;
            cpa16(&Wb[r * 48 + c * 8], &W[(size_t)(n0 + r) * 1024 + k0 + c * 8]);
        }
    };

    ISSUE(0); asm volatile("cp.async.commit_group;\n");

    for (int it = 0; it < 32; it++) {
        asm volatile("cp.async.wait_group 0;\n");
        __syncthreads();
        if (it + 1 < 32) {
            ISSUE(it + 1);
            asm volatile("cp.async.commit_group;\n");
        }

        const __half* Ab = Apool + (it & 1) * AS_ST;
        const __half* Wb = Wpool + (it & 1) * WS_ST;
        #pragma unroll
        for (int kk = 0; kk < 32; kk += 16) {
            unsigned a[4][4], bf[4][2];
            #pragma unroll
            for (int mt = 0; mt < 4; mt++) {
                int rb = wm * 64 + mt * 16;
                uint2 lo = *(const uint2*)&Ab[(rb + g    ) * 48 + kk + 4 * tg];
                uint2 hi = *(const uint2*)&Ab[(rb + g + 8) * 48 + kk + 4 * tg];
                a[mt][0] = lo.x; a[mt][1] = hi.x;
                a[mt][2] = lo.y; a[mt][3] = hi.y;
            }
            #pragma unroll
            for (int nt = 0; nt < 4; nt++) {
                int nb = wn * 32 + nt * 8;
                uint2 bp = *(const uint2*)&Wb[(nb + g) * 48 + kk + 4 * tg];
                bf[nt][0] = bp.x; bf[nt][1] = bp.y;
            }
            #pragma unroll
            for (int mt = 0; mt < 4; mt++)
                #pragma unroll
                for (int nt = 0; nt < 4; nt++)
                    mma16(acc[mt][nt], a[mt], bf[nt][0], bf[nt][1]);
        }
    }

    #pragma unroll
    for (int mt = 0; mt < 4; mt++) {
        #pragma unroll
        for (int nt = 0; nt < 4; nt++) {
            int colL = wn * 32 + nt * 8 + 2 * tg;
            int rA = m0 + wm * 64 + mt * 16 + g;
            int rB = rA + 8;
            float c0 = acc[mt][nt][0], c1 = acc[mt][nt][1];
            float c2 = acc[mt][nt][2], c3 = acc[mt][nt][3];
            if (mode == 0) {
                float* out = (float*)C;
                float b0 = bias[n0 + colL], b1 = bias[n0 + colL + 1];
                *(float2*)&out[(size_t)rA * 1024 + n0 + colL] = make_float2(c0 + b0, c1 + b1);
                *(float2*)&out[(size_t)rB * 1024 + n0 + colL] = make_float2(c2 + b0, c3 + b1);
            } else {
                int gc = n0 + colL;
                int h = gc >> 6, d = gc & 63;
                int bA = rA >> 11, tA = rA & 2047;
                int bB = rB >> 11, tB = rB & 2047;
                if (blockIdx.z == 2) {
                    __half* V = (__half*)C;     // [b][h][d][tperm]
                    size_t baseA = ((size_t)(bA * Hh + h) * HDIM + d) * Tt;
                    size_t baseB = ((size_t)(bB * Hh + h) * HDIM + d) * Tt;
                    int tpA = (tA & ~15) + kpos16(tA & 15);
                    int tpB = (tB & ~15) + kpos16(tB & 15);
                    V[baseA      + tpA] = __float2half(c0);
                    V[baseA + Tt + tpA] = __float2half(c1);
                    V[baseB      + tpB] = __float2half(c2);
                    V[baseB + Tt + tpB] = __float2half(c3);
                } else {
                    float sc = (blockIdx.z == 0) ? QSC : 1.0f;
                    __half* Ch = (__half*)C;
                    __half* dA = &Ch[((size_t)(bA * Hh + h) * Tt + tA) * HDIM];
                    __half* dB = &Ch[((size_t)(bB * Hh + h) * Tt + tB) * HDIM];
                    int p = (d & ~15) + kpos16(d & 15);   // even -> half2 aligned
                    *(__half2*)&dA[p] = __floats2half2_rn(c0 * sc, c1 * sc);
                    *(__half2*)&dB[p] = __floats2half2_rn(c2 * sc, c3 * sc);
                }
            }
        }
    }
}

// ---------------------------------------------------------------------------
// Flash attention (fp16 mma.sync m16n8k16), PERSISTENT (304 CTAs, LPT).
// Q pre-scaled fp16 d-perm16; K fp16 d-perm16; V^T fp16 t-perm16.
// S C-frag == PV A-frag layout -> P pack is 16 cvt.f16x2, no shuffles.
// smem: Qs[128][80] | Ks[2][64][80] | Vt[2][64][80] halves = 61440 B.
// ---------------------------------------------------------------------------
#define FSMEM ((128*80 + 2*64*80 + 2*64*80) * 2)   // 61440

__global__ __launch_bounds__(256, 2)
void flash_mma(const __half* __restrict__ q, const __half* __restrict__ k,
               const __half* __restrict__ vt, __half* __restrict__ ctx)
{
    extern __shared__ __half smh[];
    __half* Qs  = smh;                     // [128][80]
    __half* Ks  = smh + 128 * 80;          // [2][64][80]
    __half* Vtb = Ks + 2 * 64 * 80;        // [2][64][80]
    __shared__ int s_item;

    const int tid  = threadIdx.x;
    const int lane = tid & 31, warp = tid >> 5;
    const int g = lane >> 2, tg = lane & 3;
    const int wq = warp * 16;

    for (;;) {
        if (tid == 0) s_item = atomicAdd(&g_ctr, 1);
        __syncthreads();
        const int item = s_item;
        if (item >= NFLASH) break;

        const int qt = 15 - (item >> 5);      // heaviest first
        const int bh = item & 31;
        const int h = bh & 15, b = bh >> 4;
        const int q0 = qt * 128;

        const size_t bho = (size_t)(b * Hh + h) * (Tt * HDIM);
        const __half* qb = q + bho;
        const __half* kb = k + bho;
        const __half* vp = vt + bho;          // [d][tperm]

        // Q tile via cp.async (pre-scaled, perm16)
        #pragma unroll
        for (int i = 0; i < 4; i++) {
            int id = i * 256 + tid;
            int r = id >> 3, c = id & 7;
            cpa16(&Qs[r * 80 + c * 8], &qb[(size_t)(q0 + r) * HDIM + c * 8]);
        }

        auto ISSKV = [&](int kt, int s) {
            const int k0 = kt * 64;
            #pragma unroll
            for (int i = 0; i < 2; i++) {
                int id = i * 256 + tid;
                int r = id >> 3, c = id & 7;
                cpa16(&Ks [s * (64*80) + r * 80 + c * 8], &kb[(size_t)(k0 + r) * HDIM + c * 8]);
                cpa16(&Vtb[s * (64*80) + r * 80 + c * 8], &vp[(size_t)r * Tt + k0 + c * 8]);
            }
        };

        float mrow[2] = {-1e30f, -1e30f};
        float lrow[2] = {0.f, 0.f};
        float O[8][4];
        #pragma unroll
        for (int nt = 0; nt < 8; nt++)
            #pragma unroll
            for (int j = 0; j < 4; j++) O[nt][j] = 0.f;

        const int ktmax = 2 * qt + 1;
        ISSKV(0, 0); asm volatile("cp.async.commit_group;\n");

        for (int kt = 0; kt <= ktmax; kt++) {
            const int s = kt & 1;
            const int k0 = kt * 64;
            asm volatile("cp.async.wait_group 0;\n");
            __syncthreads();
            if (kt < ktmax) {
                ISSKV(kt + 1, s ^ 1);
                asm volatile("cp.async.commit_group;\n");
            }

            if (k0 <= q0 + wq + 15) {
                const __half* Kb = Ks  + s * (64*80);
                const __half* Vb = Vtb + s * (64*80);

                float S[8][4];
                #pragma unroll
                for (int nt = 0; nt < 8; nt++)
                    #pragma unroll
                    for (int j = 0; j < 4; j++) S[nt][j] = 0.f;

                // S = Q K^T  (4 chunks of k16)
                #pragma unroll
                for (int c4 = 0; c4 < 64; c4 += 16) {
                    uint2 qlo = *(const uint2*)&Qs[(wq + g    ) * 80 + c4 + 4 * tg];
                    uint2 qhi = *(const uint2*)&Qs[(wq + g + 8) * 80 + c4 + 4 * tg];
                    unsigned a[4] = { qlo.x, qhi.x, qlo.y, qhi.y };
                    #pragma unroll
                    for (int nt = 0; nt < 8; nt++) {
                        uint2 kp = *(const uint2*)&Kb[(nt * 8 + g) * 80 + c4 + 4 * tg];
                        mma16(S[nt], a, kp.x, kp.y);
                    }
                }

                // causal mask (log2-domain scores)
                if (k0 + 63 > q0 + wq) {
                    int qA = q0 + wq + g, qB = qA + 8;
                    #pragma unroll
                    for (int nt = 0; nt < 8; nt++) {
                        int c = k0 + nt * 8 + 2 * tg;
                        if (c     > qA) S[nt][0] = -1e30f;
                        if (c + 1 > qA) S[nt][1] = -1e30f;
                        if (c     > qB) S[nt][2] = -1e30f;
                        if (c + 1 > qB) S[nt][3] = -1e30f;
                    }
                }

                // online softmax, exp2 domain (rows g, g+8)
                float mA = -1e30f, mB = -1e30f;
                #pragma unroll
                for (int nt = 0; nt < 8; nt++) {
                    mA = fmaxf(mA, fmaxf(S[nt][0], S[nt][1]));
                    mB = fmaxf(mB, fmaxf(S[nt][2], S[nt][3]));
                }
                #pragma unroll
                for (int o = 1; o <= 2; o <<= 1) {
                    mA = fmaxf(mA, __shfl_xor_sync(0xffffffffu, mA, o));
                    mB = fmaxf(mB, __shfl_xor_sync(0xffffffffu, mB, o));
                }
                float nmA = fmaxf(mrow[0], mA), nmB = fmaxf(mrow[1], mB);
                float sA = 0.f, sB = 0.f;
                #pragma unroll
                for (int nt = 0; nt < 8; nt++) {
                    S[nt][0] = ex2(S[nt][0] - nmA);
                    S[nt][1] = ex2(S[nt][1] - nmA);
                    S[nt][2] = ex2(S[nt][2] - nmB);
                    S[nt][3] = ex2(S[nt][3] - nmB);
                    sA += S[nt][0] + S[nt][1];
                    sB += S[nt][2] + S[nt][3];
                }
                #pragma unroll
                for (int o = 1; o <= 2; o <<= 1) {
                    sA += __shfl_xor_sync(0xffffffffu, sA, o);
                    sB += __shfl_xor_sync(0xffffffffu, sB, o);
                }
                float scA = ex2(mrow[0] - nmA), scB = ex2(mrow[1] - nmB);
                lrow[0] = lrow[0] * scA + sA;  mrow[0] = nmA;
                lrow[1] = lrow[1] * scB + sB;  mrow[1] = nmB;
                #pragma unroll
                for (int nt = 0; nt < 8; nt++) {
                    O[nt][0] *= scA; O[nt][1] *= scA;
                    O[nt][2] *= scB; O[nt][3] *= scB;
                }

                // O += P V : S C-frags pack DIRECTLY to fp16 A-frags
                #pragma unroll
                for (int j = 0; j < 4; j++) {
                    unsigned a[4];
                    a[0] = h2u(S[2*j    ][0], S[2*j    ][1]);
                    a[1] = h2u(S[2*j    ][2], S[2*j    ][3]);
                    a[2] = h2u(S[2*j + 1][0], S[2*j + 1][1]);
                    a[3] = h2u(S[2*j + 1][2], S[2*j + 1][3]);
                    #pragma unroll
                    for (int nt = 0; nt < 8; nt++) {
                        uint2 vv = *(const uint2*)&Vb[(nt * 8 + g) * 80 + 16 * j + 4 * tg];
                        mma16(O[nt], a, vv.x, vv.y);
                    }
                }
            }
        }

        // normalize + write ctx half, k-perm16 (A of Wo gemm)
        float invA = 1.0f / lrow[0], invB = 1.0f / lrow[1];
        int tA = q0 + wq + g, tB = tA + 8;
        __half* rowA = &ctx[((size_t)b * Tt + tA) * Dd];
        __half* rowB = &ctx[((size_t)b * Tt + tB) * Dd];
        #pragma unroll
        for (int nt = 0; nt < 8; nt++) {
            int c = h * HDIM + nt * 8 + 2 * tg;
            int p = (c & ~15) + kpos16(c & 15);       // even
            *(__half2*)&rowA[p] = __floats2half2_rn(O[nt][0] * invA, O[nt][1] * invA);
            *(__half2*)&rowB[p] = __floats2half2_rn(O[nt][2] * invB, O[nt][3] * invB);
        }
    }
}

// ---------------------------------------------------------------------------
extern "C" void kernel_launch(void* const* d_in, const int* in_sizes, int n_in,
                              void* d_out, int out_size)
{
    const float* x  = (const float*)d_in[0];
    const float* Wq = (const float*)d_in[1];
    const float* Wk = (const float*)d_in[2];
    const float* Wv = (const float*)d_in[3];
    const float* Wo = (const float*)d_in[4];
    const float* bo = (const float*)d_in[5];
    float* out = (float*)d_out;

    __half *pq, *pk, *pvt, *pctx, *pxh, *pwt;
    cudaGetSymbolAddress((void**)&pq,   g_qh);
    cudaGetSymbolAddress((void**)&pk,   g_kh);
    cudaGetSymbolAddress((void**)&pvt,  g_vth);
    cudaGetSymbolAddress((void**)&pctx, g_ctxh);
    cudaGetSymbolAddress((void**)&pxh,  g_xh);
    cudaGetSymbolAddress((void**)&pwt,  g_wth);
    __half* wt0 = pwt;
    __half* wt1 = pwt + (size_t)Dd*Dd;
    __half* wt2 = pwt + 2*(size_t)Dd*Dd;
    __half* wt3 = pwt + 3*(size_t)Dd*Dd;

    cudaFuncSetAttribute(gemm_mma,  cudaFuncAttributeMaxDynamicSharedMemorySize, GSMEM);
    cudaFuncSetAttribute(flash_mma, cudaFuncAttributeMaxDynamicSharedMemorySize, FSMEM);

    prep<<<dim3(32, 32, 5), 256>>>(x, Wq, Wk, Wv, Wo);

    gemm_mma<<<dim3(Dd/128, MTOT/128, 3), 256, GSMEM>>>(
        pxh, wt0, wt1, wt2, pq, pk, pvt, nullptr, 1);

    flash_mma<<<304, 256, FSMEM>>>(pq, pk, pvt, pctx);

    gemm_mma<<<dim3(Dd/128, MTOT/128, 1), 256, GSMEM>>>(
        pctx, wt3, nullptr, nullptr, out, nullptr, nullptr, bo, 0);
}